// round 3
// baseline (speedup 1.0000x reference)
#include <cuda_runtime.h>
#include <math.h>

#define T_  4
#define B_  16
#define CIN 3
#define HIMG 64
#define WIMG 64
#define NN  6
#define COUT 128
#define HP  32
#define WPx 32
#define NH  4
#define HDm 32
#define BN_EPS 1e-5f
#define V_TH 1.0f

#define PLANE (HP*WPx)
#define OUTSZ (B_*COUT*PLANE)

typedef unsigned long long u64;

__device__ __forceinline__ u64 bcast2(float v) {
    u64 r; asm("mov.b64 %0, {%1,%1};" : "=l"(r) : "f"(v)); return r;
}
__device__ __forceinline__ void ffma2(u64 &d, u64 a, u64 b) {
    asm("fma.rn.f32x2 %0, %1, %2, %0;" : "+l"(d) : "l"(a), "l"(b));
}
__device__ __forceinline__ void unpack2(float &lo, float &hi, u64 v) {
    asm("mov.b64 {%0,%1}, %2;" : "=f"(lo), "=f"(hi) : "l"(v));
}

// ---------------- persistent device state ----------------
__device__ float g_v0[B_*COUT*HIMG*WIMG];
__device__ float g_vnodes[(NN-1)*B_*COUT*PLANE];
__device__ float g_traces[B_*NN*COUT];
__device__ __align__(16) float g_out0p[B_*COUT*34*36];
__device__ float g_mean0[B_*COUT];
__device__ float g_feat0[B_*COUT];
__device__ float g_nodemean[(NN-1)*B_*COUT];
__device__ float g_c[B_*NN];
__device__ __align__(16) float g_wt[(NN-1)*COUT*9*COUT]; // [n][ci][k][co]
__device__ float g_spk[(NN-1)*OUTSZ];

// ---------------- init ----------------
__global__ void k_init() {
    long long idx = (long long)blockIdx.x * blockDim.x + threadIdx.x;
    long long stride = (long long)gridDim.x * blockDim.x;
    for (long long i = idx; i < (long long)B_*COUT*HIMG*WIMG; i += stride) g_v0[i] = 0.f;
    for (long long i = idx; i < (long long)(NN-1)*B_*COUT*PLANE; i += stride) g_vnodes[i] = 0.f;
    for (long long i = idx; i < (long long)B_*COUT*34*36; i += stride) g_out0p[i] = 0.f;
    for (long long i = idx; i < B_*NN*COUT; i += stride) g_traces[i] = 0.f;
    for (long long i = idx; i < B_*COUT; i += stride) g_mean0[i] = 0.f;
}

// ---------------- weight reorg ----------------
__global__ void k_wreorg(const float* __restrict__ convs_w) {
    int idx = blockIdx.x * blockDim.x + threadIdx.x;
    if (idx >= (NN-1)*COUT*9*COUT) return;
    int co = idx % COUT; int t = idx / COUT;
    int k = t % 9; t /= 9;
    int ci = t % COUT; int n = t / COUT;
    g_wt[idx] = convs_w[(((long long)n*COUT + co)*COUT + ci)*9 + k];
}

// ---------------- K1: conv0 + bn0 + plif0 + pool ----------------
__global__ __launch_bounds__(256)
void k1_conv0(const float* __restrict__ x_t, const float* __restrict__ w0,
              const float* __restrict__ bg, const float* __restrict__ bb,
              const float* __restrict__ bm, const float* __restrict__ bv,
              const float* __restrict__ plifw, const float* __restrict__ outw,
              float* __restrict__ out_t)
{
    const int bx = blockIdx.x;
    const int cog = bx >> 1;
    const int half = bx & 1;
    const int b = blockIdx.y;
    const int tid = threadIdx.x;

    __shared__ __align__(16) float s_x[CIN*34*68];
    __shared__ float s_w[8*27];
    __shared__ float s_sum[8];

    if (tid < 8) s_sum[tid] = 0.f;
    if (tid < 216) s_w[tid] = w0[cog*216 + tid];

    for (int idx = tid; idx < CIN*34*66; idx += 256) {
        int ci = idx / (34*66);
        int rem = idx % (34*66);
        int y = rem / 66, xc = rem % 66;
        int gy = half*32 - 1 + y, gx = xc - 1;
        float v = 0.f;
        if (gy >= 0 && gy < HIMG && gx >= 0 && gx < WIMG)
            v = x_t[(b*CIN + ci)*HIMG*WIMG + gy*WIMG + gx];
        s_x[(ci*34 + y)*68 + xc] = v;
    }

    float bnA[8], bnB[8];
    #pragma unroll
    for (int co = 0; co < 8; ++co) {
        int cg_ = cog*8 + co;
        float inv = rsqrtf(bv[cg_] + BN_EPS);
        bnA[co] = bg[cg_] * inv;
        bnB[co] = bb[cg_] - bm[cg_] * bnA[co];
    }
    const float sig0 = 1.f / (1.f + expf(-plifw[0]));
    const float ws0  = 1.f / (1.f + expf(-outw[0]));

    __syncthreads();

    float lsum[8];
    #pragma unroll
    for (int co = 0; co < 8; ++co) lsum[co] = 0.f;

    #pragma unroll
    for (int q = 0; q < 2; ++q) {
        int p = tid + 256*q;
        int php = p >> 5, pwp = p & 31;
        int hp = half*16 + php;
        int wp = pwp;
        int ty0 = php*2, tx0 = pwp*2;

        float xin[CIN][4][4];
        #pragma unroll
        for (int ci = 0; ci < CIN; ++ci)
            #pragma unroll
            for (int r = 0; r < 4; ++r)
                #pragma unroll
                for (int c = 0; c < 4; ++c)
                    xin[ci][r][c] = s_x[(ci*34 + ty0 + r)*68 + tx0 + c];

        #pragma unroll
        for (int co = 0; co < 8; ++co) {
            float s00=0.f, s01=0.f, s10=0.f, s11=0.f;
            #pragma unroll
            for (int ci = 0; ci < CIN; ++ci) {
                #pragma unroll
                for (int kh = 0; kh < 3; ++kh)
                    #pragma unroll
                    for (int kw = 0; kw < 3; ++kw) {
                        float wv = s_w[co*27 + ci*9 + kh*3 + kw];
                        s00 = fmaf(xin[ci][kh  ][kw  ], wv, s00);
                        s01 = fmaf(xin[ci][kh  ][kw+1], wv, s01);
                        s10 = fmaf(xin[ci][kh+1][kw  ], wv, s10);
                        s11 = fmaf(xin[ci][kh+1][kw+1], wv, s11);
                    }
            }
            int cg_ = cog*8 + co;
            long long vbase = ((long long)(b*COUT + cg_)*HIMG + hp*2)*WIMG + wp*2;
            float spsum = 0.f;
            float convs4[4] = {s00, s01, s10, s11};
            long long voff[4] = {0, 1, WIMG, WIMG+1};
            #pragma unroll
            for (int e = 0; e < 4; ++e) {
                float xc = convs4[e]*bnA[co] + bnB[co];
                long long vi = vbase + voff[e];
                float vp = g_v0[vi];
                float v = vp + (xc - vp)*sig0;
                float sk = (v >= V_TH) ? 1.f : 0.f;
                g_v0[vi] = v * (1.f - sk);
                spsum += sk;
            }
            float pooled = spsum * 0.25f;
            g_out0p[((b*COUT + cg_)*34 + hp + 1)*36 + (wp + 1)] = pooled;
            out_t[(b*COUT + cg_)*PLANE + hp*WPx + wp] = ws0 * pooled;
            lsum[co] += pooled;
        }
    }

    #pragma unroll
    for (int co = 0; co < 8; ++co) {
        float v = lsum[co];
        #pragma unroll
        for (int off = 16; off > 0; off >>= 1)
            v += __shfl_down_sync(0xffffffffu, v, off);
        if ((tid & 31) == 0) atomicAdd(&s_sum[co], v);
    }
    __syncthreads();
    if (tid < 8)
        atomicAdd(&g_mean0[b*COUT + cog*8 + tid], s_sum[tid] * (1.f/1024.f));
}

// ---------------- K2: graph machinery, latency-optimized ----------------
// grid (B), 512 threads. All 128-dots split 4-way across adjacent lanes.
__global__ __launch_bounds__(512)
void k2_graph(const float* __restrict__ ft_w, const float* __restrict__ ft_b,
              const float* __restrict__ gat_W, const float* __restrict__ gat_a)
{
    const int b = blockIdx.x;
    const int tid = threadIdx.x;
    const int q = tid & 3;

    __shared__ float s_tr[NN][COUT];
    __shared__ float s_m0[COUT];
    __shared__ float s_hp[NN][COUT];
    __shared__ float s_e1[NN*NH], s_e2[NN*NH];
    __shared__ float s_attn[NN*NN];
    __shared__ float s_Sp[NN*NN];
    __shared__ float s_adj[NN*NN];
    __shared__ float s_dis[NN];
    __shared__ float s_op[NN*NN];

    for (int i = tid; i < NN*COUT; i += 512)
        ((float*)s_tr)[i] = g_traces[b*NN*COUT + i];
    if (tid < COUT) s_m0[tid] = g_mean0[b*COUT + tid];
    __syncthreads();

    // feat0: 128 outputs x 4-way split
    {
        int out = tid >> 2;
        float part = 0.f;
        #pragma unroll 8
        for (int i = 0; i < 32; ++i) {
            int c = q*32 + i;
            part = fmaf(s_m0[c], ft_w[out*COUT + c], part);
        }
        part += __shfl_xor_sync(0xffffffffu, part, 1);
        part += __shfl_xor_sync(0xffffffffu, part, 2);
        if (q == 0) {
            float f0 = fmaxf(part + ft_b[out], 0.f);
            g_feat0[b*COUT + out] = f0;
            float t0 = 0.6f * s_tr[0][out] + 0.4f * f0;
            s_tr[0][out] = t0;
            g_traces[(b*NN + 0)*COUT + out] = t0;
        }
    }
    __syncthreads();

    // hp = traces @ gat_W.T : 768 outputs x 4-way = 3072 tasks, 6 waves
    #pragma unroll
    for (int w = 0; w < 6; ++w) {
        int task = tid + 512*w;
        int out = task >> 2;       // 0..767
        int qq = task & 3;
        int n = out >> 7, r = out & 127;
        float part = 0.f;
        #pragma unroll 8
        for (int i = 0; i < 32; ++i) {
            int c = qq*32 + i;
            part = fmaf(s_tr[n][c], gat_W[r*COUT + c], part);
        }
        part += __shfl_xor_sync(0xffffffffu, part, 1);
        part += __shfl_xor_sync(0xffffffffu, part, 2);
        if (qq == 0) s_hp[n][r] = part;
    }
    __syncthreads();

    if (tid < NN*NH) {
        int n = tid >> 2, h = tid & 3;
        float a1 = 0.f, a2 = 0.f;
        #pragma unroll
        for (int d = 0; d < HDm; ++d) {
            float v = s_hp[n][h*HDm + d];
            a1 = fmaf(v, gat_a[h*2*HDm + d], a1);
            a2 = fmaf(v, gat_a[h*2*HDm + HDm + d], a2);
        }
        s_e1[tid] = a1; s_e2[tid] = a2;
    }
    __syncthreads();

    if (tid < NN*NN) {
        int i = tid / NN, j = tid % NN;
        float s = 0.f;
        #pragma unroll
        for (int h = 0; h < NH; ++h) {
            float v1 = s_e1[i*NH + h] + s_e2[j*NH + h];
            v1 = (v1 > 0.f) ? v1 : 0.2f * v1;
            float v2 = s_e1[j*NH + h] + s_e2[i*NH + h];
            v2 = (v2 > 0.f) ? v2 : 0.2f * v2;
            s += 0.5f * (v1 + v2);
        }
        s_attn[tid] = s * (1.f / NH);
    }
    __syncthreads();

    if (tid < NN) {
        float z[NN], m = -1e30f;
        #pragma unroll
        for (int j = 0; j < NN; ++j) { z[j] = s_attn[tid*NN + j] * 100.f; m = fmaxf(m, z[j]); }
        float ssum = 0.f;
        #pragma unroll
        for (int j = 0; j < NN; ++j) { z[j] = expf(z[j] - m); ssum += z[j]; }
        float inv = 1.f / ssum;
        float v[NN];
        #pragma unroll
        for (int j = 0; j < NN; ++j) v[j] = z[j] * inv;
        float m1 = -1.f, m2 = -1.f, m3 = -1.f;
        #pragma unroll
        for (int j = 0; j < NN; ++j) {
            float x = v[j];
            if (x > m1) { m3 = m2; m2 = m1; m1 = x; }
            else if (x > m2) { m3 = m2; m2 = x; }
            else if (x > m3) { m3 = x; }
        }
        #pragma unroll
        for (int j = 0; j < NN; ++j)
            s_Sp[tid*NN + j] = (v[j] >= m3) ? v[j] : 0.f;
    }
    __syncthreads();

    if (tid < NN*NN) {
        int i = tid / NN, j = tid % NN;
        s_adj[tid] = 0.5f * (s_Sp[i*NN + j] + s_Sp[j*NN + i]);
    }
    __syncthreads();

    if (tid < NN) {
        float d = 0.f;
        #pragma unroll
        for (int j = 0; j < NN; ++j) d += s_adj[tid*NN + j];
        s_dis[tid] = 1.f / sqrtf(d + 1e-6f);
    }
    __syncthreads();

    if (tid < NN*NN) {
        int i = tid / NN, j = tid % NN;
        s_op[tid] = s_dis[i] * s_adj[tid] * s_dis[j];
    }
    __syncthreads();

    if (tid < NN) {
        float c = 0.f;
        #pragma unroll
        for (int j = 0; j < NN; ++j)
            c = fmaf(s_op[tid*NN + j], s_op[j*NN + 0], c);
        g_c[b*NN + tid] = c;
    }
}

// ---------------- K3: node convs (f32x2, wk hoisted for both co-pairs) ----------------
__global__ __launch_bounds__(256, 2)
void k3_nodes(const float* __restrict__ bg, const float* __restrict__ bb,
              const float* __restrict__ bm, const float* __restrict__ bv,
              const float* __restrict__ plifw)
{
    const int cog  = blockIdx.x;
    const int node = blockIdx.y + 1;
    const int b    = blockIdx.z;
    const int tid  = threadIdx.x;
    const int sp   = tid & 63;
    const int cg   = tid >> 6;
    const int hp0  = (sp >> 3) * 4, wp0 = (sp & 7) * 4;
    const int coBase = cog * 16 + cg * 4;

    __shared__ __align__(16) float s_in[4*34*36];
    __shared__ __align__(16) float s_w[4*9*16];
    __shared__ float s_red[16];

    if (tid < 16) s_red[tid] = 0.f;

    u64 acc[2][16];
    #pragma unroll
    for (int up = 0; up < 2; ++up)
        #pragma unroll
        for (int p = 0; p < 16; ++p) acc[up][p] = 0ULL;

    const float4* inbase4 = (const float4*)(g_out0p + ((long long)b*COUT)*1224);
    const float*  wtbase  = g_wt + ((long long)(node-1)*COUT)*9*COUT + cog*16;

    for (int ci0 = 0; ci0 < COUT; ci0 += 4) {
        __syncthreads();
        {
            const float4* src = inbase4 + (long long)ci0*306;
            float4* dst = (float4*)s_in;
            #pragma unroll 5
            for (int i = tid; i < 1224; i += 256) dst[i] = src[i];
        }
        for (int i = tid; i < 144; i += 256) {
            int cc = i / 36, rem = i % 36;
            int k = rem >> 2, f = rem & 3;
            ((float4*)s_w)[i] = *(const float4*)(wtbase + ((long long)(ci0+cc)*9 + k)*COUT + f*4);
        }
        __syncthreads();

        #pragma unroll
        for (int cc = 0; cc < 4; ++cc) {
            const float* base_in = s_in + cc*1224 + hp0*36 + wp0;
            const float* base_w  = s_w + cc*144 + cg*4;

            u64 wk[2][9];
            #pragma unroll
            for (int up = 0; up < 2; ++up)
                #pragma unroll
                for (int k = 0; k < 9; ++k)
                    wk[up][k] = *(const u64*)(base_w + k*16 + 2*up);

            #pragma unroll
            for (int r = 0; r < 6; ++r) {
                const float* rp = base_in + r*36;
                float4 a4 = *(const float4*)rp;
                float2 a2 = *(const float2*)(rp + 4);
                u64 xb[6];
                xb[0] = bcast2(a4.x); xb[1] = bcast2(a4.y);
                xb[2] = bcast2(a4.z); xb[3] = bcast2(a4.w);
                xb[4] = bcast2(a2.x); xb[5] = bcast2(a2.y);
                #pragma unroll
                for (int up = 0; up < 2; ++up) {
                    #pragma unroll
                    for (int kh = 0; kh < 3; ++kh) {
                        int ph = r - kh;
                        if (ph < 0 || ph > 3) continue;
                        #pragma unroll
                        for (int kw = 0; kw < 3; ++kw) {
                            u64 w2 = wk[up][kh*3 + kw];
                            #pragma unroll
                            for (int pw = 0; pw < 4; ++pw)
                                ffma2(acc[up][ph*4 + pw], xb[pw + kw], w2);
                        }
                    }
                }
            }
        }
    }

    const float cscale = g_c[b*NN + node];
    const float sig = 1.f / (1.f + expf(-plifw[node]));

    float lsum[4] = {0.f, 0.f, 0.f, 0.f};
    #pragma unroll
    for (int up = 0; up < 2; ++up) {
        #pragma unroll
        for (int e = 0; e < 2; ++e) {
            int co = coBase + 2*up + e;
            int bi = (node - 1)*COUT + co;
            float inv = rsqrtf(bv[bi] + BN_EPS);
            float A = bg[bi] * inv;
            float Bc = bb[bi] - bm[bi] * A;
            long long vbase = (((long long)(node-1)*B_ + b)*COUT + co)*PLANE;
            long long sbase = (long long)(node-1)*OUTSZ + ((long long)(b*COUT + co))*PLANE;
            float ls = 0.f;
            #pragma unroll
            for (int p = 0; p < 16; ++p) {
                int ph = p >> 2, pw = p & 3;
                float lo, hi;
                unpack2(lo, hi, acc[up][p]);
                float y = (e == 0 ? lo : hi) * cscale;
                float ybn = y * A + Bc;
                int off = (hp0 + ph)*WPx + (wp0 + pw);
                float vp = g_vnodes[vbase + off];
                float v = vp + (ybn - vp)*sig;
                float sk = (v >= V_TH) ? 1.f : 0.f;
                g_vnodes[vbase + off] = v * (1.f - sk);
                g_spk[sbase + off] = sk;
                ls += sk;
            }
            lsum[2*up + e] = ls;
        }
    }

    #pragma unroll
    for (int l = 0; l < 4; ++l) {
        float v = lsum[l];
        #pragma unroll
        for (int off = 16; off > 0; off >>= 1)
            v += __shfl_down_sync(0xffffffffu, v, off);
        if ((tid & 31) == 0) atomicAdd(&s_red[cg*4 + l], v);
    }
    __syncthreads();
    if (tid < 16)
        g_nodemean[((node-1)*B_ + b)*COUT + cog*16 + tid] = s_red[tid] * (1.f/1024.f);
}

// ---------------- K5: combine node spikes into output ----------------
__global__ __launch_bounds__(256)
void k5_combine(const float* __restrict__ outw, float* __restrict__ out_t)
{
    int i = blockIdx.x * 256 + threadIdx.x;
    if (i >= OUTSZ) return;
    float v = out_t[i];
    #pragma unroll
    for (int n = 1; n < NN; ++n) {
        float ws = 1.f / (1.f + expf(-outw[n]));
        v = fmaf(ws, g_spk[(long long)(n-1)*OUTSZ + i], v);
    }
    out_t[i] = v;
}

// ---------------- K4: node feats + trace update, latency-optimized ----------------
// grid (B), 512 threads.
__global__ __launch_bounds__(512)
void k4_feats(const float* __restrict__ ft_w, const float* __restrict__ ft_b)
{
    const int b = blockIdx.x;
    const int tid = threadIdx.x;

    __shared__ float s_m[NN-1][COUT];
    __shared__ float s_f[NN-1][COUT];

    for (int i = tid; i < (NN-1)*COUT; i += 512)
        ((float*)s_m)[i] = g_nodemean[(i >> 7)*B_*COUT + b*COUT + (i & 127)];
    __syncthreads();

    // 640 outputs x 4-way split = 2560 tasks, 5 waves
    #pragma unroll
    for (int w = 0; w < 5; ++w) {
        int task = tid + 512*w;
        int out = task >> 2;      // 0..639
        int qq = task & 3;
        int n = out >> 7, r = out & 127;
        float part = 0.f;
        #pragma unroll 8
        for (int i = 0; i < 32; ++i) {
            int c = qq*32 + i;
            part = fmaf(s_m[n][c], ft_w[r*COUT + c], part);
        }
        part += __shfl_xor_sync(0xffffffffu, part, 1);
        part += __shfl_xor_sync(0xffffffffu, part, 2);
        if (qq == 0) s_f[n][r] = fmaxf(part + ft_b[r], 0.f);
    }
    __syncthreads();

    if (tid < NN*COUT) {
        int n = tid >> 7, r = tid & 127;
        float fval = (n == 0) ? g_feat0[b*COUT + r] : s_f[n-1][r];
        int idx = (b*NN + n)*COUT + r;
        g_traces[idx] = 0.6f * g_traces[idx] + 0.4f * fval;
    }
    if (tid < COUT) g_mean0[b*COUT + tid] = 0.f;
}

// ---------------- host launch ----------------
extern "C" void kernel_launch(void* const* d_in, const int* in_sizes, int n_in,
                              void* d_out, int out_size)
{
    const float* x       = (const float*)d_in[0];
    const float* conv0_w = (const float*)d_in[1];
    const float* bn0_g   = (const float*)d_in[2];
    const float* bn0_b   = (const float*)d_in[3];
    const float* bn0_m   = (const float*)d_in[4];
    const float* bn0_v   = (const float*)d_in[5];
    const float* convs_w = (const float*)d_in[6];
    const float* bns_g   = (const float*)d_in[7];
    const float* bns_b   = (const float*)d_in[8];
    const float* bns_m   = (const float*)d_in[9];
    const float* bns_v   = (const float*)d_in[10];
    const float* plif_w  = (const float*)d_in[11];
    const float* ft_w    = (const float*)d_in[12];
    const float* ft_b    = (const float*)d_in[13];
    const float* gat_W   = (const float*)d_in[14];
    const float* gat_a   = (const float*)d_in[15];
    const float* out_w   = (const float*)d_in[16];
    float* out = (float*)d_out;

    k_init<<<2048, 256>>>();
    k_wreorg<<<((NN-1)*COUT*9*COUT + 255)/256, 256>>>(convs_w);

    for (int t = 0; t < T_; ++t) {
        const float* xt = x + (long long)t * B_ * CIN * HIMG * WIMG;
        float* out_t = out + (long long)t * OUTSZ;

        k1_conv0<<<dim3(32, B_), 256>>>(xt, conv0_w, bn0_g, bn0_b, bn0_m, bn0_v,
                                        plif_w, out_w, out_t);
        k2_graph<<<B_, 512>>>(ft_w, ft_b, gat_W, gat_a);
        k3_nodes<<<dim3(8, NN-1, B_), 256>>>(bns_g, bns_b, bns_m, bns_v, plif_w);
        k5_combine<<<(OUTSZ + 255)/256, 256>>>(out_w, out_t);
        k4_feats<<<B_, 512>>>(ft_w, ft_b);
    }
}